// round 9
// baseline (speedup 1.0000x reference)
#include <cuda_runtime.h>
#include <cstdint>

#define DIMS 2048
#define NCLS 4000
#define NROWS 32768
#define NTHR 256
#define MOM 0.9f
#define EPS 1e-12f
#define CAP 64   // per-class bucket capacity; P(Poisson(8.2) > 64) ~ 1e-40

// Graph-safe __device__ scratch (no allocs). g_icnt is zero at module load and
// re-zeroed by gather_finalize after each use -> clean state per launch/replay.
__device__ int g_icnt[2][NCLS];
__device__ int g_rowlist[2][NCLS][CAP];

// Packed four-value block reduction: warp shfl -> smem partials -> single sync
// -> every thread sums the 8 warp partials itself. 2 barriers total.
__device__ __forceinline__ float4 blockReduceSum4(float4 v, float4* sh4) {
    int lane = threadIdx.x & 31;
    int w = threadIdx.x >> 5;
    #pragma unroll
    for (int o = 16; o > 0; o >>= 1) {
        v.x += __shfl_xor_sync(0xffffffffu, v.x, o);
        v.y += __shfl_xor_sync(0xffffffffu, v.y, o);
        v.z += __shfl_xor_sync(0xffffffffu, v.z, o);
        v.w += __shfl_xor_sync(0xffffffffu, v.w, o);
    }
    if (lane == 0) sh4[w] = v;
    __syncthreads();
    float4 r = make_float4(0.f, 0.f, 0.f, 0.f);
    #pragma unroll
    for (int i = 0; i < NTHR / 32; ++i) {
        r.x += sh4[i].x; r.y += sh4[i].y; r.z += sh4[i].z; r.w += sh4[i].w;
    }
    __syncthreads();   // sh4 reusable afterwards
    return r;
}

// --------------------------------------------- single-pass hist + bucket
__global__ void fill(const int* __restrict__ idv, const int* __restrict__ idr) {
    int m = blockIdx.y;
    int i = blockIdx.x * blockDim.x + threadIdx.x;
    if (i < NROWS) {
        int id = (m == 0 ? idv : idr)[i];
        int pos = atomicAdd(&g_icnt[m][id], 1);
        if (pos < CAP) g_rowlist[m][id][pos] = i;
    }
}

__device__ __forceinline__ float sumsq8(float4 a, float4 b) {
    return a.x*a.x + a.y*a.y + a.z*a.z + a.w*a.w
         + b.x*b.x + b.y*b.y + b.z*b.z + b.w*b.w;
}

// ------------------------------------------- fused gather + finalize
// One block per (class, modality). Chunks of 4 rows, two phases:
//   phase 1: burst-load 4 rows (L1-caching), keep only sumsq partials
//   (one packed float4 block-reduce)
//   phase 2: re-read the 4 rows from L1/L2 (evict-first) and scale-accumulate.
__global__ __launch_bounds__(NTHR, 4) void gather_finalize(
    const float* __restrict__ fv, const float* __restrict__ fr,
    const float* __restrict__ vism, const float* __restrict__ irm,
    float* __restrict__ out)
{
    __shared__ float4 sh4[NTHR / 32];
    __shared__ int sh_rows[CAP];
    const int m = blockIdx.y;
    const int c = blockIdx.x;
    const int t = threadIdx.x;

    const float* feat = (m == 0 ? fv : fr);
    const int rawcnt = g_icnt[m][c];          // read by ALL threads
    const int cnt = (rawcnt < CAP) ? rawcnt : CAP;

    if (t < CAP && t < cnt) sh_rows[t] = g_rowlist[m][c][t];
    __syncthreads();

    float4 acc0 = make_float4(0.f, 0.f, 0.f, 0.f);
    float4 acc1 = make_float4(0.f, 0.f, 0.f, 0.f);

    const int nchunk = (cnt + 3) >> 2;
    for (int ch = 0; ch < nchunk; ++ch) {
        const int base = ch << 2;
        const int nr = cnt - base;   // rows in this chunk (may exceed 4 -> min)

        // ---- phase 1: burst sumsq (keeps rows in L1 for phase 2) ----
        float s0 = 0.f, s1 = 0.f, s2 = 0.f, s3 = 0.f;
        {
            if (nr > 0) {
                const float4* f = reinterpret_cast<const float4*>(
                    feat + (size_t)sh_rows[base + 0] * DIMS);
                s0 = sumsq8(__ldg(&f[t]), __ldg(&f[t + NTHR]));
            }
            if (nr > 1) {
                const float4* f = reinterpret_cast<const float4*>(
                    feat + (size_t)sh_rows[base + 1] * DIMS);
                s1 = sumsq8(__ldg(&f[t]), __ldg(&f[t + NTHR]));
            }
            if (nr > 2) {
                const float4* f = reinterpret_cast<const float4*>(
                    feat + (size_t)sh_rows[base + 2] * DIMS);
                s2 = sumsq8(__ldg(&f[t]), __ldg(&f[t + NTHR]));
            }
            if (nr > 3) {
                const float4* f = reinterpret_cast<const float4*>(
                    feat + (size_t)sh_rows[base + 3] * DIMS);
                s3 = sumsq8(__ldg(&f[t]), __ldg(&f[t + NTHR]));
            }
        }
        float4 ss = blockReduceSum4(make_float4(s0, s1, s2, s3), sh4);
        const float c0 = 1.f / fmaxf(sqrtf(ss.x), EPS);
        const float c1 = 1.f / fmaxf(sqrtf(ss.y), EPS);
        const float c2 = 1.f / fmaxf(sqrtf(ss.z), EPS);
        const float c3 = 1.f / fmaxf(sqrtf(ss.w), EPS);

        // ---- phase 2: re-read (cache hit) + scale-accumulate ----
        #define ACCROW(r, cs) do {                                          \
            const float4* _f = reinterpret_cast<const float4*>(             \
                feat + (size_t)sh_rows[base + (r)] * DIMS);                 \
            float4 _x = __ldcs(&_f[t]);                                     \
            float4 _y = __ldcs(&_f[t + NTHR]);                              \
            acc0.x += (cs) * _x.x; acc0.y += (cs) * _x.y;                   \
            acc0.z += (cs) * _x.z; acc0.w += (cs) * _x.w;                   \
            acc1.x += (cs) * _y.x; acc1.y += (cs) * _y.y;                   \
            acc1.z += (cs) * _y.z; acc1.w += (cs) * _y.w;                   \
        } while (0)
        if (nr > 0) ACCROW(0, c0);
        if (nr > 1) ACCROW(1, c1);
        if (nr > 2) ACCROW(2, c2);
        if (nr > 3) ACCROW(3, c3);
        #undef ACCROW
    }

    // Memory row loaded after the gather loop (keeps loop registers lean).
    const float4* m4 = reinterpret_cast<const float4*>(
        (m == 0 ? vism : irm) + (size_t)c * DIMS);
    float4 w0 = __ldcs(&m4[t]), w1 = __ldcs(&m4[t + NTHR]);

    const float invc = 1.f / fmaxf((float)cnt, 1.f);
    acc0.x *= invc; acc0.y *= invc; acc0.z *= invc; acc0.w *= invc;
    acc1.x *= invc; acc1.y *= invc; acc1.z *= invc; acc1.w *= invc;

    float4 ssm = blockReduceSum4(
        make_float4(sumsq8(acc0, acc1), 0.f, 0.f, 0.f), sh4);
    if (t == 0) g_icnt[m][c] = 0;    // safe: all cnt reads happened pre-barrier
    const float inm = 1.f / fmaxf(sqrtf(ssm.x), EPS);

    float4 t0, t1;
    t0.x = MOM * w0.x + (1.f - MOM) * (acc0.x * inm);
    t0.y = MOM * w0.y + (1.f - MOM) * (acc0.y * inm);
    t0.z = MOM * w0.z + (1.f - MOM) * (acc0.z * inm);
    t0.w = MOM * w0.w + (1.f - MOM) * (acc0.w * inm);
    t1.x = MOM * w1.x + (1.f - MOM) * (acc1.x * inm);
    t1.y = MOM * w1.y + (1.f - MOM) * (acc1.y * inm);
    t1.z = MOM * w1.z + (1.f - MOM) * (acc1.z * inm);
    t1.w = MOM * w1.w + (1.f - MOM) * (acc1.w * inm);

    float4 sst = blockReduceSum4(
        make_float4(sumsq8(t0, t1), 0.f, 0.f, 0.f), sh4);
    const float int_ = 1.f / fmaxf(sqrtf(sst.x), EPS);

    const bool present = (cnt > 0);
    float4 o0, o1;
    o0.x = present ? t0.x * int_ : w0.x;
    o0.y = present ? t0.y * int_ : w0.y;
    o0.z = present ? t0.z * int_ : w0.z;
    o0.w = present ? t0.w * int_ : w0.w;
    o1.x = present ? t1.x * int_ : w1.x;
    o1.y = present ? t1.y * int_ : w1.y;
    o1.z = present ? t1.z * int_ : w1.z;
    o1.w = present ? t1.w * int_ : w1.w;

    float4* o4 = reinterpret_cast<float4*>(
        out + (size_t)m * NCLS * DIMS + (size_t)c * DIMS);
    __stcs(&o4[t], o0);
    __stcs(&o4[t + NTHR], o1);
}

extern "C" void kernel_launch(void* const* d_in, const int* in_sizes, int n_in,
                              void* d_out, int out_size) {
    const float* fv   = (const float*)d_in[0];
    const float* fr   = (const float*)d_in[1];
    const int*   idv  = (const int*)d_in[2];
    const int*   idr  = (const int*)d_in[3];
    const float* vism = (const float*)d_in[4];
    const float* irm  = (const float*)d_in[5];
    float* out = (float*)d_out;

    fill<<<dim3((NROWS + 255) / 256, 2), 256>>>(idv, idr);
    gather_finalize<<<dim3(NCLS, 2), NTHR>>>(fv, fr, vism, irm, out);
}